// round 6
// baseline (speedup 1.0000x reference)
#include <cuda_runtime.h>

#define B_ 1024
#define T_ 256
#define H_ 512
#define S_ 64

// h ping-pong scratch (static device memory; no allocations anywhere)
__device__ __align__(16) float g_hbuf[2][B_ * H_];

// ---- packed f32x2 helpers (2x fp32 FMA throughput on sm_103a) ----
__device__ __forceinline__ unsigned long long pk2(float a, float b) {
    unsigned long long r;
    asm("mov.b64 %0, {%1, %2};" : "=l"(r) : "f"(a), "f"(b));
    return r;
}
__device__ __forceinline__ float2 up2(unsigned long long v) {
    float2 r;
    asm("mov.b64 {%0, %1}, %2;" : "=f"(r.x), "=f"(r.y) : "l"(v));
    return r;
}
#define FFMA2(d, a, b, c) \
    asm("fma.rn.f32x2 %0, %1, %2, %3;" : "=l"(d) : "l"(a), "l"(b), "l"(c))

// Step 0: h = relu(x[:,0] * w_in + bias), starting from h == 0.
__global__ void rnn_first(const float* __restrict__ x, const float* __restrict__ w_in,
                          const float* __restrict__ b_ih, const float* __restrict__ b_hh) {
    int idx = blockIdx.x * 256 + threadIdx.x;   // 0 .. B*H-1
    int b = idx >> 9;
    int i = idx & (H_ - 1);
    float v = x[b * T_] * w_in[i] + b_ih[i] + b_hh[i];
    g_hbuf[0][idx] = fmaxf(v, 0.0f);
}

// One recurrence step: hout = relu(xv * w_in + hin @ W^T + bias).
// R=false (warmup): xv = x[b, t].
// R=true (rollout): xv = y_b = hin[b,:] . w_fc + b_fc (fused into the K-loop),
//                   and y_b is written to yout[b*S_ + s].
// Grid: (16, 8) -> CTA tile 64 (b) x 64 (i). 256 threads, each 4b x 4i outputs
// held as f32x2 b-pairs.
template <bool R>
__global__ __launch_bounds__(256, 1) void rnn_step(
    int ping,
    const float* __restrict__ W,        // H x H row-major (W_hh)
    const float* __restrict__ w_in,     // H   (W_ih is (H,1) contiguous)
    const float* __restrict__ b_ih,
    const float* __restrict__ b_hh,
    const float* __restrict__ x, int t, // warmup input column
    const float* __restrict__ w_fc,     // H   (W_fc is (1,H) contiguous)
    const float* __restrict__ b_fc,
    float* __restrict__ yout, int s)    // rollout output
{
    __shared__ __align__(16) float As[2][16][64];  // A chunk, [j][b] transposed
    __shared__ __align__(16) float Ws[2][16][64];  // W chunk, [j][i] transposed
    __shared__ float swfc[H_];

    const float* hin  = g_hbuf[ping];
    float*       hout = g_hbuf[ping ^ 1];

    const int tid = threadIdx.x;
    const int bm0 = blockIdx.x * 64;
    const int in0 = blockIdx.y * 64;
    const int row = tid >> 2;   // 0..63
    const int q   = tid & 3;    // 0..3 -> 4 floats each

    const float* Ap = hin + (bm0 + row) * H_ + q * 4;
    const float* Wp = W   + (in0 + row) * H_ + q * 4;

    if (R) { swfc[tid] = w_fc[tid]; swfc[tid + 256] = w_fc[tid + 256]; }

    // chunk 0 -> smem buffer 0
    float4 va = *(const float4*)Ap;
    float4 vw = *(const float4*)Wp;
    As[0][q * 4 + 0][row] = va.x; As[0][q * 4 + 1][row] = va.y;
    As[0][q * 4 + 2][row] = va.z; As[0][q * 4 + 3][row] = va.w;
    Ws[0][q * 4 + 0][row] = vw.x; Ws[0][q * 4 + 1][row] = vw.y;
    Ws[0][q * 4 + 2][row] = vw.z; Ws[0][q * 4 + 3][row] = vw.w;
    __syncthreads();

    unsigned long long acc[2][4];
#pragma unroll
    for (int p = 0; p < 2; ++p)
#pragma unroll
        for (int c = 0; c < 4; ++c) acc[p][c] = 0ull;
    unsigned long long yac[2] = {0ull, 0ull};

    const int bl = (tid & 15) * 4;   // local b base (4 rows = 2 f32x2 pairs)
    const int il = (tid >> 4) * 4;   // local i base (4 cols)

    for (int kc = 0; kc < 32; ++kc) {
        const int cur = kc & 1;
        if (kc < 31) {  // prefetch next chunk to registers (hides L2 latency)
            va = *(const float4*)(Ap + (kc + 1) * 16);
            vw = *(const float4*)(Wp + (kc + 1) * 16);
        }
#pragma unroll
        for (int j = 0; j < 16; ++j) {
            ulonglong2 a2 = *(const ulonglong2*)&As[cur][j][bl];   // 4 b-values = 2 pairs
            float4 w4 = *(const float4*)&Ws[cur][j][il];           // 4 i-weights
            unsigned long long wp0 = pk2(w4.x, w4.x), wp1 = pk2(w4.y, w4.y),
                               wp2 = pk2(w4.z, w4.z), wp3 = pk2(w4.w, w4.w);
            FFMA2(acc[0][0], a2.x, wp0, acc[0][0]);
            FFMA2(acc[1][0], a2.y, wp0, acc[1][0]);
            FFMA2(acc[0][1], a2.x, wp1, acc[0][1]);
            FFMA2(acc[1][1], a2.y, wp1, acc[1][1]);
            FFMA2(acc[0][2], a2.x, wp2, acc[0][2]);
            FFMA2(acc[1][2], a2.y, wp2, acc[1][2]);
            FFMA2(acc[0][3], a2.x, wp3, acc[0][3]);
            FFMA2(acc[1][3], a2.y, wp3, acc[1][3]);
            if (R) {
                float wf = swfc[kc * 16 + j];
                unsigned long long wfp = pk2(wf, wf);
                FFMA2(yac[0], a2.x, wfp, yac[0]);
                FFMA2(yac[1], a2.y, wfp, yac[1]);
            }
        }
        if (kc < 31) {
            const int nb = cur ^ 1;
            As[nb][q * 4 + 0][row] = va.x; As[nb][q * 4 + 1][row] = va.y;
            As[nb][q * 4 + 2][row] = va.z; As[nb][q * 4 + 3][row] = va.w;
            Ws[nb][q * 4 + 0][row] = vw.x; Ws[nb][q * 4 + 1][row] = vw.y;
            Ws[nb][q * 4 + 2][row] = vw.z; Ws[nb][q * 4 + 3][row] = vw.w;
        }
        __syncthreads();
    }

    const int bg = bm0 + bl;
    const int ig = in0 + il;

    // unpack accumulators: fa[r][c] = acc for (b = bg+r, i = ig+c)
    float fa[4][4];
#pragma unroll
    for (int p = 0; p < 2; ++p)
#pragma unroll
        for (int c = 0; c < 4; ++c) {
            float2 u = up2(acc[p][c]);
            fa[2 * p][c] = u.x;
            fa[2 * p + 1][c] = u.y;
        }

    float xv[4];
    if (R) {
        float bfc = b_fc[0];
        float2 y0 = up2(yac[0]);
        float2 y1 = up2(yac[1]);
        xv[0] = y0.x + bfc; xv[1] = y0.y + bfc;
        xv[2] = y1.x + bfc; xv[3] = y1.y + bfc;
        // every i-block computes identical y (same K order) -> deterministic;
        // only block column 0, i-group 0 writes it out.
        if (in0 == 0 && il == 0) {
#pragma unroll
            for (int r = 0; r < 4; ++r) yout[(bg + r) * S_ + s] = xv[r];
        }
    } else {
#pragma unroll
        for (int r = 0; r < 4; ++r) xv[r] = x[(bg + r) * T_ + t];
    }

    float4 wi4 = *(const float4*)(w_in + ig);
    float4 bi4 = *(const float4*)(b_ih + ig);
    float4 bh4 = *(const float4*)(b_hh + ig);
    float wv[4] = {wi4.x, wi4.y, wi4.z, wi4.w};
    float bv[4] = {bi4.x + bh4.x, bi4.y + bh4.y, bi4.z + bh4.z, bi4.w + bh4.w};

#pragma unroll
    for (int r = 0; r < 4; ++r) {
        float4 hv;
        hv.x = fmaxf(fa[r][0] + xv[r] * wv[0] + bv[0], 0.0f);
        hv.y = fmaxf(fa[r][1] + xv[r] * wv[1] + bv[1], 0.0f);
        hv.z = fmaxf(fa[r][2] + xv[r] * wv[2] + bv[2], 0.0f);
        hv.w = fmaxf(fa[r][3] + xv[r] * wv[3] + bv[3], 0.0f);
        *(float4*)(hout + (bg + r) * H_ + ig) = hv;
    }
}

extern "C" void kernel_launch(void* const* d_in, const int* in_sizes, int n_in,
                              void* d_out, int out_size) {
    // metadata order: x, W_ih, W_hh, b_ih, b_hh, W_fc, b_fc, num_steps
    const float* x    = (const float*)d_in[0];
    const float* W_ih = (const float*)d_in[1];   // (H,1) -> H contiguous = w_in
    const float* W_hh = (const float*)d_in[2];   // (H,H)
    const float* b_ih = (const float*)d_in[3];
    const float* b_hh = (const float*)d_in[4];
    const float* W_fc = (const float*)d_in[5];   // (1,H) -> H contiguous
    const float* b_fc = (const float*)d_in[6];
    float* out = (float*)d_out;                  // (B, 64, 1) float32
    (void)in_sizes; (void)n_in; (void)out_size;  // num_steps fixed at 64

    // t = 0 (h starts at zero)
    rnn_first<<<(B_ * H_) / 256, 256>>>(x, W_ih, b_ih, b_hh);

    dim3 grid(16, 8);   // 128 CTAs: full 1024x512 output per step
    int ping = 0;       // rnn_first wrote g_hbuf[0]

    // warmup t = 1 .. 255
    for (int t = 1; t < T_; ++t) {
        rnn_step<false><<<grid, 256>>>(ping, W_hh, W_ih, b_ih, b_hh,
                                       x, t, nullptr, nullptr, nullptr, 0);
        ping ^= 1;
    }
    // rollout s = 0 .. 63 (y fused into the step kernel)
    for (int s = 0; s < S_; ++s) {
        rnn_step<true><<<grid, 256>>>(ping, W_hh, W_ih, b_ih, b_hh,
                                      nullptr, 0, W_fc, b_fc, out, s);
        ping ^= 1;
    }
}